// round 1
// baseline (speedup 1.0000x reference)
#include <cuda_runtime.h>
#include <cstdint>

// Problem constants
#define L_TOT      1200000
#define D_IN       64
#define D_ENC      128
#define N_CLS      10
#define JWIN       30
#define SEGS       40000
#define ROWS_PB    240          // rows per block = 8 segments = 15 m16-tiles
#define SEG_PB     8
#define NBLOCKS    (L_TOT / ROWS_PB)   // 5000
#define THREADS    256

// smem layout (floats), padded strides for bank-conflict-free frag loads
#define XS_STRIDE  68           // 64 cols + 4 pad  -> bank=(4*row+k)%32 conflict-free
#define WT_STRIDE  132          // 128 cols + 4 pad -> B frags near conflict-free
#define F_STRIDE   136          // feats/wcls pad   -> final GEMM conflict-free
#define XS_FLOATS  (ROWS_PB * XS_STRIDE)            // 16320
#define WT_FLOATS  (64 * WT_STRIDE)                 // 8448
#define FT_FLOATS  (2 * SEG_PB * F_STRIDE)          // 2176
#define WC_FLOATS  (N_CLS * F_STRIDE)               // 1360
#define SMEM_FLOATS (XS_FLOATS + WT_FLOATS + FT_FLOATS + WC_FLOATS)
#define SMEM_BYTES (SMEM_FLOATS * 4)                // 113216 B -> 2 blocks/SM

__device__ __forceinline__ uint32_t f2tf32(float f) {
    uint32_t u;
    asm("cvt.rna.tf32.f32 %0, %1;" : "=r"(u) : "f"(f));
    return u;
}

__device__ __forceinline__ void mma_tf32(float c[4],
                                         uint32_t a0, uint32_t a1, uint32_t a2, uint32_t a3,
                                         uint32_t b0, uint32_t b1) {
    asm volatile(
        "mma.sync.aligned.m16n8k8.row.col.f32.tf32.tf32.f32 "
        "{%0,%1,%2,%3}, {%4,%5,%6,%7}, {%8,%9}, {%0,%1,%2,%3};"
        : "+f"(c[0]), "+f"(c[1]), "+f"(c[2]), "+f"(c[3])
        : "r"(a0), "r"(a1), "r"(a2), "r"(a3), "r"(b0), "r"(b1));
}

__device__ __forceinline__ float warp8_reduce(float v) {
    // sum across lanes {l, l^4, l^8, ... } — the 8 lanes sharing the same mma column set
    v += __shfl_xor_sync(0xffffffffu, v, 4);
    v += __shfl_xor_sync(0xffffffffu, v, 8);
    v += __shfl_xor_sync(0xffffffffu, v, 16);
    return v;
}

__global__ __launch_bounds__(THREADS, 2)
void classifier_kernel(const float* __restrict__ x,
                       const float* __restrict__ Wloc,
                       const float* __restrict__ W,
                       float* __restrict__ out) {
    extern __shared__ float smem[];
    float* xs    = smem;                         // [240][68]  tf32 bits
    float* wt    = xs + XS_FLOATS;               // [64][132]  Wloc^T tf32 bits
    float* feats = wt + WT_FLOATS;               // [2][8][136] fp32 segment sums
    float* wcls  = feats + FT_FLOATS;            // [10][136]  fp32 classifier

    const int tid = threadIdx.x;
    const int blk = blockIdx.x;
    const long rowBase = (long)blk * ROWS_PB;

    // ---- stage Wloc^T as tf32 (round-to-nearest, unbiased) ----
    for (int i = tid; i < D_ENC * D_IN; i += THREADS) {
        int e = i >> 6, d = i & 63;
        wt[d * WT_STRIDE + e] = __uint_as_float(f2tf32(Wloc[i]));
    }
    // ---- stage classifier W (fp32, padded rows) ----
    for (int i = tid; i < N_CLS * D_ENC; i += THREADS) {
        wcls[(i >> 7) * F_STRIDE + (i & 127)] = W[i];
    }
    // ---- zero segment accumulators ----
    for (int i = tid; i < FT_FLOATS; i += THREADS) feats[i] = 0.0f;

    // ---- stage x tile (240 rows x 64), convert to tf32, padded stride ----
    const float4* x4 = reinterpret_cast<const float4*>(x + rowBase * D_IN);
    for (int i = tid; i < ROWS_PB * (D_IN / 4); i += THREADS) {   // 3840 float4
        int r = i >> 4, c4 = i & 15;
        float4 v = x4[i];
        float4 o;
        o.x = __uint_as_float(f2tf32(v.x));
        o.y = __uint_as_float(f2tf32(v.y));
        o.z = __uint_as_float(f2tf32(v.z));
        o.w = __uint_as_float(f2tf32(v.w));
        *reinterpret_cast<float4*>(xs + r * XS_STRIDE + c4 * 4) = o;
    }
    __syncthreads();

    const int lane  = tid & 31;
    const int wid   = tid >> 5;
    const int g     = wid & 1;       // m-group: 0 -> m-tiles 0..7, 1 -> 8..14
    const int strip = wid >> 1;      // 4 column strips of 32
    const int nb    = strip * 32;

    // ---- preload ALL B fragments for this warp's 32-col strip into registers ----
    // B frag (m16n8k8, col): b0 = B[k = lane%4][n = nb+8f+lane/4], b1 = k+4
    uint32_t bq[8][4][2];
    {
        const float* wtb = wt + (lane & 3) * WT_STRIDE + nb + (lane >> 2);
        #pragma unroll
        for (int ks = 0; ks < 8; ++ks) {
            #pragma unroll
            for (int f = 0; f < 4; ++f) {
                bq[ks][f][0] = __float_as_uint(wtb[ks * 8 * WT_STRIDE + f * 8]);
                bq[ks][f][1] = __float_as_uint(wtb[ks * 8 * WT_STRIDE + 4 * WT_STRIDE + f * 8]);
            }
        }
    }

    float* fg = feats + g * SEG_PB * F_STRIDE;
    const int mtBeg = g ? 8 : 0;
    const int mtEnd = g ? 15 : 8;
    const int r = lane >> 2;         // low row within m-tile for this lane

    for (int mt = mtBeg; mt < mtEnd; ++mt) {
        float acc[4][4];
        #pragma unroll
        for (int f = 0; f < 4; ++f) {
            acc[f][0] = acc[f][1] = acc[f][2] = acc[f][3] = 0.0f;
        }

        // A frags: a0 = A[row0 + lane/4][kb + lane%4]; a1 = row+8; a2 = k+4; a3 = both
        const float* xr = xs + (mt * 16 + r) * XS_STRIDE + (lane & 3);
        #pragma unroll
        for (int ks = 0; ks < 8; ++ks) {
            uint32_t a0 = __float_as_uint(xr[ks * 8]);
            uint32_t a1 = __float_as_uint(xr[8 * XS_STRIDE + ks * 8]);
            uint32_t a2 = __float_as_uint(xr[ks * 8 + 4]);
            uint32_t a3 = __float_as_uint(xr[8 * XS_STRIDE + ks * 8 + 4]);
            #pragma unroll
            for (int f = 0; f < 4; ++f) {
                mma_tf32(acc[f], a0, a1, a2, a3, bq[ks][f][0], bq[ks][f][1]);
            }
        }

        // relu
        #pragma unroll
        for (int f = 0; f < 4; ++f) {
            acc[f][0] = fmaxf(acc[f][0], 0.0f);
            acc[f][1] = fmaxf(acc[f][1], 0.0f);
            acc[f][2] = fmaxf(acc[f][2], 0.0f);
            acc[f][3] = fmaxf(acc[f][3], 0.0f);
        }

        // segment pooling: rows of this m-tile belong to 1 or 2 segments
        const int rA  = mt * 16;
        const int sLo = rA / JWIN;
        const int sHi = (rA + 15) / JWIN;

        if (sLo == sHi) {
            // whole 16-row tile in one segment: column sums
            float sum[8];
            #pragma unroll
            for (int f = 0; f < 4; ++f) {
                sum[2 * f]     = acc[f][0] + acc[f][2];
                sum[2 * f + 1] = acc[f][1] + acc[f][3];
            }
            #pragma unroll
            for (int q = 0; q < 8; ++q) sum[q] = warp8_reduce(sum[q]);
            if (lane < 4) {
                #pragma unroll
                for (int f = 0; f < 4; ++f) {
                    fg[sLo * F_STRIDE + nb + f * 8 + 2 * lane]     += sum[2 * f];
                    fg[sLo * F_STRIDE + nb + f * 8 + 2 * lane + 1] += sum[2 * f + 1];
                }
            }
        } else {
            // tile spans a segment boundary at local row b
            const int b = sHi * JWIN - rA;
            const bool pL = (r < b);
            const bool pH = (r + 8 < b);
            float lo[8], hi[8];
            #pragma unroll
            for (int f = 0; f < 4; ++f) {
                float l0 = pL ? acc[f][0] : 0.0f;
                float l1 = pL ? acc[f][1] : 0.0f;
                float l2 = pH ? acc[f][2] : 0.0f;
                float l3 = pH ? acc[f][3] : 0.0f;
                lo[2 * f]     = l0 + l2;
                lo[2 * f + 1] = l1 + l3;
                hi[2 * f]     = (acc[f][0] + acc[f][2]) - lo[2 * f];
                hi[2 * f + 1] = (acc[f][1] + acc[f][3]) - lo[2 * f + 1];
            }
            #pragma unroll
            for (int q = 0; q < 8; ++q) { lo[q] = warp8_reduce(lo[q]); hi[q] = warp8_reduce(hi[q]); }
            if (lane < 4) {
                #pragma unroll
                for (int f = 0; f < 4; ++f) {
                    fg[sLo * F_STRIDE + nb + f * 8 + 2 * lane]     += lo[2 * f];
                    fg[sLo * F_STRIDE + nb + f * 8 + 2 * lane + 1] += lo[2 * f + 1];
                    fg[sHi * F_STRIDE + nb + f * 8 + 2 * lane]     += hi[2 * f];
                    fg[sHi * F_STRIDE + nb + f * 8 + 2 * lane + 1] += hi[2 * f + 1];
                }
            }
        }
    }
    __syncthreads();

    // ---- fused classifier GEMM: out[s][c] = (1/30) * sum_e feats[s][e] * W[c][e] ----
    if (tid < SEG_PB * N_CLS) {
        const int s = tid / N_CLS;
        const int c = tid % N_CLS;
        const float* f0 = feats + s * F_STRIDE;                      // g=0 partial
        const float* f1 = feats + (SEG_PB + s) * F_STRIDE;           // g=1 partial
        const float* wr = wcls + c * F_STRIDE;
        float sum = 0.0f;
        #pragma unroll 8
        for (int e = 0; e < D_ENC; ++e) {
            sum += (f0[e] + f1[e]) * wr[e];
        }
        out[((long)blk * SEG_PB + s) * N_CLS + c] = sum * (1.0f / (float)JWIN);
    }
}

extern "C" void kernel_launch(void* const* d_in, const int* in_sizes, int n_in,
                              void* d_out, int out_size) {
    const float* x    = (const float*)d_in[0];   // [1200000, 64]
    const float* Wloc = (const float*)d_in[1];   // [128, 64]
    const float* W    = (const float*)d_in[2];   // [10, 128]
    float* out = (float*)d_out;                  // [40000, 10]

    cudaFuncSetAttribute(classifier_kernel,
                         cudaFuncAttributeMaxDynamicSharedMemorySize, SMEM_BYTES);
    classifier_kernel<<<NBLOCKS, THREADS, SMEM_BYTES>>>(x, Wloc, W, out);
}

// round 4
// speedup vs baseline: 1.0890x; 1.0890x over previous
#include <cuda_runtime.h>
#include <cstdint>

// Problem constants
#define L_TOT      1200000
#define D_IN       64
#define D_ENC      128
#define N_CLS      10
#define JWIN       30
#define ROWS_PB    240                 // 8 segments, 15 m16-tiles per block
#define SEG_PB     8
#define NBLOCKS    (L_TOT / ROWS_PB)   // 5000
#define THREADS    256
#define CHUNK_ROWS 48                  // 3 m-tiles per chunk
#define NCHUNK     (ROWS_PB / CHUNK_ROWS)   // 5
#define PF_VEC     ((CHUNK_ROWS * D_IN / 4) / THREADS)   // 3 float4 per thread

// smem layout (floats)
#define XS_STRIDE  68                  // 64 + 4 pad -> conflict-free frag LDS
#define BUF_FLOATS (CHUNK_ROWS * XS_STRIDE)       // 3264
#define F_STRIDE   136
#define FT_FLOATS  (SEG_PB * F_STRIDE)            // 1088
#define SMEM_FLOATS (2 * BUF_FLOATS + FT_FLOATS)  // 7616
#define SMEM_BYTES (SMEM_FLOATS * 4)              // 30464

__device__ __forceinline__ uint32_t f2tf32(float f) {
    uint32_t u;
    asm("cvt.rna.tf32.f32 %0, %1;" : "=r"(u) : "f"(f));
    return u;
}

__device__ __forceinline__ void mma_tf32(float c[4],
                                         uint32_t a0, uint32_t a1, uint32_t a2, uint32_t a3,
                                         uint32_t b0, uint32_t b1) {
    asm volatile(
        "mma.sync.aligned.m16n8k8.row.col.f32.tf32.tf32.f32 "
        "{%0,%1,%2,%3}, {%4,%5,%6,%7}, {%8,%9}, {%0,%1,%2,%3};"
        : "+f"(c[0]), "+f"(c[1]), "+f"(c[2]), "+f"(c[3])
        : "r"(a0), "r"(a1), "r"(a2), "r"(a3), "r"(b0), "r"(b1));
}

__device__ __forceinline__ float warp8_reduce(float v) {
    // sum across the 8 lanes sharing the same mma column pair (xor 4,8,16)
    v += __shfl_xor_sync(0xffffffffu, v, 4);
    v += __shfl_xor_sync(0xffffffffu, v, 8);
    v += __shfl_xor_sync(0xffffffffu, v, 16);
    return v;
}

__global__ __launch_bounds__(THREADS, 2)
void classifier_kernel(const float* __restrict__ x,
                       const float* __restrict__ Wloc,
                       const float* __restrict__ W,
                       float* __restrict__ out) {
    extern __shared__ float smem[];
    float* bufs  = smem;                          // 2 x [48][68] raw fp32 x rows
    float* feats = smem + 2 * BUF_FLOATS;         // [8][136] fp32 segment sums

    const int tid = threadIdx.x;
    const int blk = blockIdx.x;
    const long rowBase = (long)blk * ROWS_PB;

    // per-thread prefetch slots: i = j*256 + tid -> row i/16, float4-col i%16
    const int pr0 = tid >> 4;            // row for j=0 (j adds 16 rows)
    const int pc4 = tid & 15;

    // ---- prologue: LDG chunk 0 into registers (start DRAM immediately) ----
    float4 pf[PF_VEC];
    {
        const float4* s4 = reinterpret_cast<const float4*>(x + rowBase * D_IN);
        #pragma unroll
        for (int j = 0; j < PF_VEC; ++j)
            pf[j] = s4[j * THREADS + tid];
    }

    // ---- overlap with the LDG: zero feats, preload B fragments ----
    for (int i = tid; i < FT_FLOATS; i += THREADS) feats[i] = 0.0f;

    const int lane = tid & 31;
    const int wid  = tid >> 5;
    const int nb   = wid * 16;           // this warp's 16-column strip of D_ENC
    const int r    = lane >> 2;          // low row within m-tile for this lane

    // B frag (m16n8k8, col): n = nb + f*8 + lane/4, k = ks*8 + lane%4 (+4 for b1)
    // Wloc^T[k][n] = Wloc[n*64 + k]; L2-resident; loaded once per block.
    uint32_t bq[8][2][2];
    {
        const float* wb = Wloc + (nb + (lane >> 2)) * D_IN + (lane & 3);
        #pragma unroll
        for (int ks = 0; ks < 8; ++ks) {
            #pragma unroll
            for (int f = 0; f < 2; ++f) {
                bq[ks][f][0] = f2tf32(__ldg(wb + f * 8 * D_IN + ks * 8));
                bq[ks][f][1] = f2tf32(__ldg(wb + f * 8 * D_IN + ks * 8 + 4));
            }
        }
    }

    // ---- store chunk 0 to buffer 0 ----
    #pragma unroll
    for (int j = 0; j < PF_VEC; ++j)
        *reinterpret_cast<float4*>(bufs + (pr0 + j * 16) * XS_STRIDE + pc4 * 4) = pf[j];
    __syncthreads();

    // ---- pipelined mainloop over 5 chunks ----
    for (int c = 0; c < NCHUNK; ++c) {
        // prefetch chunk c+1 (LDGs issue now, consumed after compute)
        if (c + 1 < NCHUNK) {
            const float4* s4 = reinterpret_cast<const float4*>(
                x + (rowBase + (long)(c + 1) * CHUNK_ROWS) * D_IN);
            #pragma unroll
            for (int j = 0; j < PF_VEC; ++j)
                pf[j] = s4[j * THREADS + tid];
        }

        const float* xs = bufs + (c & 1) * BUF_FLOATS;

        #pragma unroll
        for (int mt = 0; mt < 3; ++mt) {
            float acc[2][4];
            #pragma unroll
            for (int f = 0; f < 2; ++f)
                acc[f][0] = acc[f][1] = acc[f][2] = acc[f][3] = 0.0f;

            // A frags: a0 = A[r][k], a1 = A[r+8][k], a2 = A[r][k+4], a3 = A[r+8][k+4]
            const float* xr = xs + (mt * 16 + r) * XS_STRIDE + (lane & 3);
            #pragma unroll
            for (int ks = 0; ks < 8; ++ks) {
                uint32_t a0 = f2tf32(xr[ks * 8]);
                uint32_t a1 = f2tf32(xr[8 * XS_STRIDE + ks * 8]);
                uint32_t a2 = f2tf32(xr[ks * 8 + 4]);
                uint32_t a3 = f2tf32(xr[8 * XS_STRIDE + ks * 8 + 4]);
                #pragma unroll
                for (int f = 0; f < 2; ++f)
                    mma_tf32(acc[f], a0, a1, a2, a3, bq[ks][f][0], bq[ks][f][1]);
            }

            // relu
            #pragma unroll
            for (int f = 0; f < 2; ++f) {
                acc[f][0] = fmaxf(acc[f][0], 0.0f);
                acc[f][1] = fmaxf(acc[f][1], 0.0f);
                acc[f][2] = fmaxf(acc[f][2], 0.0f);
                acc[f][3] = fmaxf(acc[f][3], 0.0f);
            }

            // segment pooling (block-local; JWIN=30 > 16 -> at most one boundary)
            const int rA  = c * CHUNK_ROWS + mt * 16;
            const int sLo = rA / JWIN;
            const int sHi = (rA + 15) / JWIN;

            if (sLo == sHi) {
                float sum[4];
                #pragma unroll
                for (int f = 0; f < 2; ++f) {
                    sum[2 * f]     = acc[f][0] + acc[f][2];
                    sum[2 * f + 1] = acc[f][1] + acc[f][3];
                }
                #pragma unroll
                for (int q = 0; q < 4; ++q) sum[q] = warp8_reduce(sum[q]);
                if (lane < 4) {
                    #pragma unroll
                    for (int f = 0; f < 2; ++f) {
                        feats[sLo * F_STRIDE + nb + f * 8 + 2 * lane]     += sum[2 * f];
                        feats[sLo * F_STRIDE + nb + f * 8 + 2 * lane + 1] += sum[2 * f + 1];
                    }
                }
            } else {
                const int b = sHi * JWIN - rA;      // boundary row within tile
                const bool pL = (r < b);
                const bool pH = (r + 8 < b);
                float lo[4], hi[4];
                #pragma unroll
                for (int f = 0; f < 2; ++f) {
                    float l0 = pL ? acc[f][0] : 0.0f;
                    float l1 = pL ? acc[f][1] : 0.0f;
                    float l2 = pH ? acc[f][2] : 0.0f;
                    float l3 = pH ? acc[f][3] : 0.0f;
                    lo[2 * f]     = l0 + l2;
                    lo[2 * f + 1] = l1 + l3;
                    hi[2 * f]     = (acc[f][0] + acc[f][2]) - lo[2 * f];
                    hi[2 * f + 1] = (acc[f][1] + acc[f][3]) - lo[2 * f + 1];
                }
                #pragma unroll
                for (int q = 0; q < 4; ++q) { lo[q] = warp8_reduce(lo[q]); hi[q] = warp8_reduce(hi[q]); }
                if (lane < 4) {
                    #pragma unroll
                    for (int f = 0; f < 2; ++f) {
                        feats[sLo * F_STRIDE + nb + f * 8 + 2 * lane]     += lo[2 * f];
                        feats[sLo * F_STRIDE + nb + f * 8 + 2 * lane + 1] += lo[2 * f + 1];
                        feats[sHi * F_STRIDE + nb + f * 8 + 2 * lane]     += hi[2 * f];
                        feats[sHi * F_STRIDE + nb + f * 8 + 2 * lane + 1] += hi[2 * f + 1];
                    }
                }
            }
        }

        // stage chunk c+1 into the other buffer (prev readers of it finished
        // at the barrier ending iteration c-1; current readers use buf(c&1))
        if (c + 1 < NCHUNK) {
            float* nx = bufs + ((c + 1) & 1) * BUF_FLOATS;
            #pragma unroll
            for (int j = 0; j < PF_VEC; ++j)
                *reinterpret_cast<float4*>(nx + (pr0 + j * 16) * XS_STRIDE + pc4 * 4) = pf[j];
        }
        __syncthreads();
    }

    // ---- fused classifier: out[s][cc] = (1/30) * sum_e feats[s][e] * W[cc][e] ----
    if (tid < SEG_PB * N_CLS) {
        const int s  = tid / N_CLS;
        const int cc = tid % N_CLS;
        const float* fs = feats + s * F_STRIDE;
        const float* wr = W + cc * D_ENC;
        float sum = 0.0f;
        #pragma unroll 8
        for (int e = 0; e < D_ENC; ++e)
            sum += fs[e] * __ldg(wr + e);
        out[((long)blk * SEG_PB + s) * N_CLS + cc] = sum * (1.0f / (float)JWIN);
    }
}

extern "C" void kernel_launch(void* const* d_in, const int* in_sizes, int n_in,
                              void* d_out, int out_size) {
    const float* x    = (const float*)d_in[0];   // [1200000, 64]
    const float* Wloc = (const float*)d_in[1];   // [128, 64]
    const float* W    = (const float*)d_in[2];   // [10, 128]
    float* out = (float*)d_out;                  // [40000, 10]

    cudaFuncSetAttribute(classifier_kernel,
                         cudaFuncAttributeMaxDynamicSharedMemorySize, SMEM_BYTES);
    classifier_kernel<<<NBLOCKS, THREADS, SMEM_BYTES>>>(x, Wloc, W, out);
}

// round 7
// speedup vs baseline: 1.2079x; 1.1092x over previous
#include <cuda_runtime.h>
#include <cstdint>

// Problem constants
#define L_TOT      1200000
#define D_IN       64
#define D_ENC      128
#define N_CLS      10
#define JWIN       30
#define ROWS_PB    240                 // 8 segments, 15 m16-tiles per block
#define SEG_PB     8
#define NBLOCKS    (L_TOT / ROWS_PB)   // 5000
#define THREADS    256
#define CHUNK_ROWS 48                  // 3 m-tiles per chunk
#define NCHUNK     (ROWS_PB / CHUNK_ROWS)   // 5
#define PF_VEC     ((CHUNK_ROWS * D_IN / 4) / THREADS)   // 3 float4 per thread

// Permuted smem layout: xs[row][q*QP + t] = tf32(x[row][q + 4*t]), q=0..3, t=0..15
//  -> each lane's A-fragment elements (fixed q) are contiguous: LDS.128 loads.
//  QP=20 (16 payload + 4 pad), RS=80 -> LDS.128 phases tile all 32 banks.
#define QP         20
#define RS         80
#define BUF_FLOATS (CHUNK_ROWS * RS)              // 3840
#define F_STRIDE   136
#define FT_FLOATS  (SEG_PB * F_STRIDE)            // 1088
#define SMEM_FLOATS (2 * BUF_FLOATS + FT_FLOATS)  // 8768
#define SMEM_BYTES (SMEM_FLOATS * 4)              // 35072 -> 3 CTAs/SM

__device__ __forceinline__ uint32_t f2tf32(float f) {
    uint32_t u;
    asm("cvt.rna.tf32.f32 %0, %1;" : "=r"(u) : "f"(f));
    return u;
}

__device__ __forceinline__ void mma_tf32(float c[4],
                                         uint32_t a0, uint32_t a1, uint32_t a2, uint32_t a3,
                                         uint32_t b0, uint32_t b1) {
    asm volatile(
        "mma.sync.aligned.m16n8k8.row.col.f32.tf32.tf32.f32 "
        "{%0,%1,%2,%3}, {%4,%5,%6,%7}, {%8,%9}, {%0,%1,%2,%3};"
        : "+f"(c[0]), "+f"(c[1]), "+f"(c[2]), "+f"(c[3])
        : "r"(a0), "r"(a1), "r"(a2), "r"(a3), "r"(b0), "r"(b1));
}

__device__ __forceinline__ float warp8_reduce(float v) {
    v += __shfl_xor_sync(0xffffffffu, v, 4);
    v += __shfl_xor_sync(0xffffffffu, v, 8);
    v += __shfl_xor_sync(0xffffffffu, v, 16);
    return v;
}

__global__ __launch_bounds__(THREADS, 3)
void classifier_kernel(const float* __restrict__ x,
                       const float* __restrict__ Wloc,
                       const float* __restrict__ W,
                       float* __restrict__ out) {
    extern __shared__ float smem[];
    float* bufs  = smem;                          // 2 x [48][80] tf32-bits
    float* feats = smem + 2 * BUF_FLOATS;         // [8][136] fp32 segment sums

    const int tid = threadIdx.x;
    const int blk = blockIdx.x;
    const long rowBase = (long)blk * ROWS_PB;

    // staging slots: i = j*256 + tid -> row i/16, float4-col i%16
    const int pr0 = tid >> 4;
    const int pc4 = tid & 15;

    // ---- prologue: LDG chunk 0 (start DRAM immediately) ----
    float4 pf[PF_VEC];
    {
        const float4* s4 = reinterpret_cast<const float4*>(x + rowBase * D_IN);
        #pragma unroll
        for (int j = 0; j < PF_VEC; ++j)
            pf[j] = s4[j * THREADS + tid];
    }

    // ---- overlap: zero feats, preload B fragments ----
    for (int i = tid; i < FT_FLOATS; i += THREADS) feats[i] = 0.0f;

    const int lane = tid & 31;
    const int wid  = tid >> 5;
    const int nb   = wid * 16;           // 16-column strip of D_ENC per warp
    const int r    = lane >> 2;
    const int q    = lane & 3;

    // B frag (m16n8k8, col): n = nb + f*8 + lane/4, k = ks*8 + q (+4 for b1)
    uint32_t bq[8][2][2];
    {
        const float* wb = Wloc + (nb + r) * D_IN + q;
        #pragma unroll
        for (int ks = 0; ks < 8; ++ks) {
            #pragma unroll
            for (int f = 0; f < 2; ++f) {
                bq[ks][f][0] = f2tf32(__ldg(wb + f * 8 * D_IN + ks * 8));
                bq[ks][f][1] = f2tf32(__ldg(wb + f * 8 * D_IN + ks * 8 + 4));
            }
        }
    }

    // ---- stage chunk 0 (convert + permute scatter) ----
    #pragma unroll
    for (int j = 0; j < PF_VEC; ++j) {
        float* b0 = bufs + (pr0 + j * 16) * RS + pc4;
        b0[0 * QP] = __uint_as_float(f2tf32(pf[j].x));
        b0[1 * QP] = __uint_as_float(f2tf32(pf[j].y));
        b0[2 * QP] = __uint_as_float(f2tf32(pf[j].z));
        b0[3 * QP] = __uint_as_float(f2tf32(pf[j].w));
    }
    __syncthreads();

    // ---- pipelined mainloop over 5 chunks ----
    for (int c = 0; c < NCHUNK; ++c) {
        if (c + 1 < NCHUNK) {
            const float4* s4 = reinterpret_cast<const float4*>(
                x + (rowBase + (long)(c + 1) * CHUNK_ROWS) * D_IN);
            #pragma unroll
            for (int j = 0; j < PF_VEC; ++j)
                pf[j] = s4[j * THREADS + tid];
        }

        const float* xs = bufs + (c & 1) * BUF_FLOATS;

        #pragma unroll
        for (int mt = 0; mt < 3; ++mt) {
            float acc[2][4];
            #pragma unroll
            for (int f = 0; f < 2; ++f)
                acc[f][0] = acc[f][1] = acc[f][2] = acc[f][3] = 0.0f;

            // lane's contiguous A run: t=0..15 at xs[(mt*16+r)*RS + q*QP]
            const uint4* lo4 = reinterpret_cast<const uint4*>(
                xs + (mt * 16 + r) * RS + q * QP);
            const uint4* hi4 = reinterpret_cast<const uint4*>(
                xs + (mt * 16 + r + 8) * RS + q * QP);

            #pragma unroll
            for (int j = 0; j < 4; ++j) {
                uint4 lo = lo4[j];              // t=4j..4j+3: ks=2j (x=a0,y=a2), ks=2j+1 (z=a0,w=a2)
                uint4 hi = hi4[j];
                #pragma unroll
                for (int f = 0; f < 2; ++f)
                    mma_tf32(acc[f], lo.x, hi.x, lo.y, hi.y,
                             bq[2 * j][f][0], bq[2 * j][f][1]);
                #pragma unroll
                for (int f = 0; f < 2; ++f)
                    mma_tf32(acc[f], lo.z, hi.z, lo.w, hi.w,
                             bq[2 * j + 1][f][0], bq[2 * j + 1][f][1]);
            }

            // relu
            #pragma unroll
            for (int f = 0; f < 2; ++f) {
                acc[f][0] = fmaxf(acc[f][0], 0.0f);
                acc[f][1] = fmaxf(acc[f][1], 0.0f);
                acc[f][2] = fmaxf(acc[f][2], 0.0f);
                acc[f][3] = fmaxf(acc[f][3], 0.0f);
            }

            // segment pooling (at most one boundary per 16-row tile)
            const int rA  = c * CHUNK_ROWS + mt * 16;
            const int sLo = rA / JWIN;
            const int sHi = (rA + 15) / JWIN;

            if (sLo == sHi) {
                float sum[4];
                #pragma unroll
                for (int f = 0; f < 2; ++f) {
                    sum[2 * f]     = acc[f][0] + acc[f][2];
                    sum[2 * f + 1] = acc[f][1] + acc[f][3];
                }
                #pragma unroll
                for (int t = 0; t < 4; ++t) sum[t] = warp8_reduce(sum[t]);
                if (lane < 4) {
                    #pragma unroll
                    for (int f = 0; f < 2; ++f) {
                        feats[sLo * F_STRIDE + nb + f * 8 + 2 * lane]     += sum[2 * f];
                        feats[sLo * F_STRIDE + nb + f * 8 + 2 * lane + 1] += sum[2 * f + 1];
                    }
                }
            } else {
                const int b = sHi * JWIN - rA;
                const bool pL = (r < b);
                const bool pH = (r + 8 < b);
                float lo[4], hi[4];
                #pragma unroll
                for (int f = 0; f < 2; ++f) {
                    float l0 = pL ? acc[f][0] : 0.0f;
                    float l1 = pL ? acc[f][1] : 0.0f;
                    float l2 = pH ? acc[f][2] : 0.0f;
                    float l3 = pH ? acc[f][3] : 0.0f;
                    lo[2 * f]     = l0 + l2;
                    lo[2 * f + 1] = l1 + l3;
                    hi[2 * f]     = (acc[f][0] + acc[f][2]) - lo[2 * f];
                    hi[2 * f + 1] = (acc[f][1] + acc[f][3]) - lo[2 * f + 1];
                }
                #pragma unroll
                for (int t = 0; t < 4; ++t) { lo[t] = warp8_reduce(lo[t]); hi[t] = warp8_reduce(hi[t]); }
                if (lane < 4) {
                    #pragma unroll
                    for (int f = 0; f < 2; ++f) {
                        feats[sLo * F_STRIDE + nb + f * 8 + 2 * lane]     += lo[2 * f];
                        feats[sLo * F_STRIDE + nb + f * 8 + 2 * lane + 1] += lo[2 * f + 1];
                        feats[sHi * F_STRIDE + nb + f * 8 + 2 * lane]     += hi[2 * f];
                        feats[sHi * F_STRIDE + nb + f * 8 + 2 * lane + 1] += hi[2 * f + 1];
                    }
                }
            }
        }

        // stage chunk c+1 into the other buffer (its prior readers finished
        // at the barrier ending iteration c-1)
        if (c + 1 < NCHUNK) {
            float* nx = bufs + ((c + 1) & 1) * BUF_FLOATS;
            #pragma unroll
            for (int j = 0; j < PF_VEC; ++j) {
                float* b0 = nx + (pr0 + j * 16) * RS + pc4;
                b0[0 * QP] = __uint_as_float(f2tf32(pf[j].x));
                b0[1 * QP] = __uint_as_float(f2tf32(pf[j].y));
                b0[2 * QP] = __uint_as_float(f2tf32(pf[j].z));
                b0[3 * QP] = __uint_as_float(f2tf32(pf[j].w));
            }
        }
        __syncthreads();
    }

    // ---- fused classifier: out[s][cc] = (1/30) * sum_e feats[s][e] * W[cc][e] ----
    if (tid < SEG_PB * N_CLS) {
        const int s  = tid / N_CLS;
        const int cc = tid % N_CLS;
        const float* fs = feats + s * F_STRIDE;
        const float* wr = W + cc * D_ENC;
        float sum = 0.0f;
        #pragma unroll 8
        for (int e = 0; e < D_ENC; ++e)
            sum += fs[e] * __ldg(wr + e);
        out[((long)blk * SEG_PB + s) * N_CLS + cc] = sum * (1.0f / (float)JWIN);
    }
}

extern "C" void kernel_launch(void* const* d_in, const int* in_sizes, int n_in,
                              void* d_out, int out_size) {
    const float* x    = (const float*)d_in[0];   // [1200000, 64]
    const float* Wloc = (const float*)d_in[1];   // [128, 64]
    const float* W    = (const float*)d_in[2];   // [10, 128]
    float* out = (float*)d_out;                  // [40000, 10]

    cudaFuncSetAttribute(classifier_kernel,
                         cudaFuncAttributeMaxDynamicSharedMemorySize, SMEM_BYTES);
    classifier_kernel<<<NBLOCKS, THREADS, SMEM_BYTES>>>(x, Wloc, W, out);
}